// round 9
// baseline (speedup 1.0000x reference)
#include <cuda_runtime.h>
#include <cuda_bf16.h>
#include <cstdint>

// GlobalPoolDistance: patch-RBF MMD, single fused persistent kernel (R9).
// MMA computes the exp2 argument directly:
//   A row i = [C2*a_0..C2*a_26, 1, -u_i, 0..]   (u = ||a||^2 * log2e/SIG2)
//   B row j = [b_0..b_26,      -v_j, 1, 0..]
//   acc(i,j) = C2*<a,b> - u - v = -log2e*||a-b||^2/SIG2 ;  K = exp2(acc).
// Epilogue skip threshold -30 (deterministic bound; see R7).
// R9: CTA tile 128x64, 32x32 warp slices -> 3 CTAs/SM (occ 37.5%).
// Sym decomposition with 64-wide tiles: tj<2i weight 2; tj in {2i,2i+1}
// (straddle pair) weight 1 each -- together they tile the diagonal block.

#define TILE 128
#define BTILE 64
#define NPATCH 3844
#define NTILES 31
#define NROWS (NTILES * TILE)                     // 3968
#define BATCH 8
#define ROW_U4 4
#define STAGE_U4 (4 * BATCH * NROWS * ROW_U4)
#define XY_CHUNKS 1984                            // 8*31 strips x 8 chunks
#define SYM_CHUNKS_PER 136
#define CHUNKS (XY_CHUNKS + 16 * SYM_CHUNKS_PER)  // 4160
#define WORKERS 444                               // 148 SMs x 3 CTAs
#define STAGE_TASKS (2 * BATCH * NROWS)           // 63488

__device__ uint4 g_stage[STAGE_U4];
__device__ float g_partials[WORKERS];
__device__ unsigned int g_bar1;
__device__ unsigned int g_ticket;
__device__ unsigned int g_done;

__device__ __forceinline__ uint32_t smem_to_u32(const void* p) {
    uint32_t a;
    asm("{ .reg .u64 t; cvta.to.shared.u64 t, %1; cvt.u32.u64 %0, t; }"
        : "=r"(a) : "l"(p));
    return a;
}
__device__ __forceinline__ void cp_async16(uint32_t smem, const void* gptr) {
    asm volatile("cp.async.cg.shared.global [%0], [%1], 16;"
                 :: "r"(smem), "l"(gptr) : "memory");
}
#define CP_COMMIT() asm volatile("cp.async.commit_group;" ::: "memory")
#define CP_WAIT0()  asm volatile("cp.async.wait_group 0;" ::: "memory")

__device__ __forceinline__ void ldsm_x4(uint32_t& r0, uint32_t& r1,
                                        uint32_t& r2, uint32_t& r3, uint32_t a) {
    asm volatile("ldmatrix.sync.aligned.m8n8.x4.shared.b16 {%0,%1,%2,%3}, [%4];"
                 : "=r"(r0), "=r"(r1), "=r"(r2), "=r"(r3) : "r"(a));
}
__device__ __forceinline__ void mma16816(float* d,
                                         uint32_t a0, uint32_t a1, uint32_t a2, uint32_t a3,
                                         uint32_t b0, uint32_t b1) {
    asm volatile("mma.sync.aligned.m16n8k16.row.col.f32.bf16.bf16.f32 "
                 "{%0,%1,%2,%3}, {%4,%5,%6,%7}, {%8,%9}, {%0,%1,%2,%3};"
                 : "+f"(d[0]), "+f"(d[1]), "+f"(d[2]), "+f"(d[3])
                 : "r"(a0), "r"(a1), "r"(a2), "r"(a3), "r"(b0), "r"(b1));
}

struct __align__(1024) Smem {
    uint4 A[512];          // 8 KB A tile (128 rows x 64B)
    uint4 B[4][256];       // 4-slot B ring, 4 KB each (64 rows x 64B)
    float red[8];
    unsigned int ticket;
    unsigned int lastflag;
};

__global__ void __launch_bounds__(256, 3)
mmd_fused(const float* __restrict__ x, const float* __restrict__ y,
          float* __restrict__ out) {
    __shared__ Smem sm;
    const int tid = threadIdx.x;
    const int wid = tid >> 5;
    const int lane = tid & 31;

    const float K1f = 4.9479492581208223f;        // log2e / 0.2916
    const float C2f = 9.8958985162416446f;        // 2*log2e / 0.2916

    // ================= Phase 1: stage operand rows =================
    {
        int gtid = blockIdx.x * 256 + tid;
        if (gtid < STAGE_TASKS) {
            int n = gtid % NROWS;
            int t2 = gtid / NROWS;
            int b = t2 & 7;
            int img = t2 >> 3;
            const float* im = img ? y : x;

            float rv[27];
            float u = 0.0f;
            bool valid = (n < NPATCH);
            if (valid) {
                int i = n / 62;
                int j = n - i * 62;
                const float* p = im + b * 12288 + (i << 6) + j;
                float sq = 0.0f;
                #pragma unroll
                for (int c = 0; c < 3; c++)
                    #pragma unroll
                    for (int rr = 0; rr < 3; rr++)
                        #pragma unroll
                        for (int ss = 0; ss < 3; ss++) {
                            float v = p[c * 4096 + (rr << 6) + ss];
                            sq = fmaf(v, v, sq);
                            rv[c * 9 + rr * 3 + ss] = v;
                        }
                u = sq * K1f;
            } else {
                #pragma unroll
                for (int k = 0; k < 27; k++) rv[k] = 0.0f;
            }
            uint32_t sw = (uint32_t)(n >> 1) & 3u;

            #pragma unroll
            for (int form = 0; form < 2; form++) {
                float rowv[32];
                #pragma unroll
                for (int k = 0; k < 27; k++)
                    rowv[k] = form ? rv[k] : (C2f * rv[k]);
                float nu = valid ? -u : -1e30f;
                if (form) { rowv[27] = nu;   rowv[28] = 1.0f; }
                else      { rowv[27] = 1.0f; rowv[28] = nu;   }
                rowv[29] = rowv[30] = rowv[31] = 0.0f;
                uint32_t wds[16];
                #pragma unroll
                for (int q = 0; q < 16; q++) {
                    __nv_bfloat162 h2 = __floats2bfloat162_rn(rowv[2*q], rowv[2*q+1]);
                    wds[q] = *reinterpret_cast<uint32_t*>(&h2);
                }
                int ver = form * 2 + img;
                int base = ((ver * BATCH + b) * NROWS + n) * ROW_U4;
                #pragma unroll
                for (int c = 0; c < 4; c++)
                    g_stage[base + (c ^ sw)] =
                        make_uint4(wds[4*c], wds[4*c+1], wds[4*c+2], wds[4*c+3]);
            }
        }
        __threadfence();
        __syncthreads();
        if (tid == 0) {
            atomicAdd(&g_bar1, 1u);
            unsigned int v;
            do {
                asm volatile("ld.acquire.gpu.global.u32 %0, [%1];"
                             : "=r"(v) : "l"(&g_bar1));
                if (v >= WORKERS) break;
                __nanosleep(64);
            } while (true);
        }
        __syncthreads();
        __threadfence();
    }

    // ================= Phase 2: persistent tile loop =================
    const int mg = wid & 3;          // row group: rows mg*32..+31 of A tile
    const int ng = wid >> 2;         // col group: B rows ng*32..+31
    const uint32_t a_base = smem_to_u32(sm.A);
    const uint32_t b_ring = smem_to_u32(sm.B);    // 4 slots x 4096 B

    uint32_t offA[2][2];
    #pragma unroll
    for (int mt = 0; mt < 2; mt++)
        #pragma unroll
        for (int k = 0; k < 2; k++) {
            int rowA = mg * 32 + mt * 16 + (lane & 15);
            int ch = k * 2 + (lane >> 4);
            int swz = ch ^ ((rowA >> 1) & 3);
            offA[mt][k] = (uint32_t)(rowA * 64 + swz * 16);
        }
    uint32_t offB[2];
    #pragma unroll
    for (int k = 0; k < 2; k++) {
        int rloc = (lane & 7) + ((lane >> 4) << 3);
        int rowB = ng * 32 + rloc;
        int ch = k * 2 + ((lane >> 3) & 1);
        int swz = ch ^ ((rowB >> 1) & 3);
        offB[k] = (uint32_t)(rowB * 64 + swz * 16);
    }

    float s = 0.0f;
    uint32_t af[2][2][4];

    // compute one 128x64 tile against B ring slot `slot`
    auto compute_tile = [&](int slot, int ti, int tj, bool sym) {
        const uint32_t bb = b_ring + (uint32_t)(slot * 4096);
        float acc[2][4][4];
        #pragma unroll
        for (int mt = 0; mt < 2; mt++)
            #pragma unroll
            for (int nt = 0; nt < 4; nt++)
                #pragma unroll
                for (int r = 0; r < 4; r++) acc[mt][nt][r] = 0.0f;

        #pragma unroll
        for (int k = 0; k < 2; k++)
            #pragma unroll
            for (int p = 0; p < 2; p++) {
                uint32_t b0, b1, b2, b3;
                ldsm_x4(b0, b1, b2, b3, bb + offB[k] + (uint32_t)(p * 1024));
                mma16816(acc[0][2*p],   af[0][k][0], af[0][k][1], af[0][k][2], af[0][k][3], b0, b1);
                mma16816(acc[0][2*p+1], af[0][k][0], af[0][k][1], af[0][k][2], af[0][k][3], b2, b3);
                mma16816(acc[1][2*p],   af[1][k][0], af[1][k][1], af[1][k][2], af[1][k][3], b0, b1);
                mma16816(acc[1][2*p+1], af[1][k][0], af[1][k][1], af[1][k][2], af[1][k][3], b2, b3);
            }

        // guard max tree over the 32 args
        float t8[8];
        #pragma unroll
        for (int mt = 0; mt < 2; mt++)
            #pragma unroll
            for (int nt = 0; nt < 4; nt++)
                t8[mt * 4 + nt] = fmaxf(fmaxf(acc[mt][nt][0], acc[mt][nt][1]),
                                        fmaxf(acc[mt][nt][2], acc[mt][nt][3]));
        #pragma unroll
        for (int st = 4; st > 0; st >>= 1)
            #pragma unroll
            for (int i2 = 0; i2 < 4; i2++)
                if (i2 < st) t8[i2] = fmaxf(t8[i2], t8[i2 + st]);

        if (__any_sync(0xffffffffu, t8[0] > -30.0f)) {
            // straddle tiles (tj>>1 == ti) contain the diagonal
            bool diagTile = sym && ((tj >> 1) == ti);
            float w = sym ? ((tj < 2 * ti) ? 2.0f : 1.0f) : -2.0f;
            int rbase = mg * 32 + (lane >> 2);
            int cbase = ng * 32 + ((lane & 3) << 1);
            int dshift = (tj & 1) << 6;      // diag: rl == (tj&1)*64 + cl
            float ts = 0.0f;
            #pragma unroll
            for (int mt = 0; mt < 2; mt++)
                #pragma unroll
                for (int nt = 0; nt < 4; nt++)
                    #pragma unroll
                    for (int r = 0; r < 4; r++) {
                        int rl = rbase + mt * 16 + ((r >> 1) << 3);
                        int cl = cbase + nt * 8 + (r & 1);
                        bool isd = diagTile && (rl == dshift + cl) &&
                                   (ti * TILE + rl < NPATCH);
                        float e;
                        asm("ex2.approx.ftz.f32 %0, %1;" : "=f"(e)
                            : "f"(acc[mt][nt][r]));
                        ts += isd ? 1.0f : e;
                    }
            s = fmaf(w, ts, s);
        }
    };

    for (;;) {
        __syncthreads();
        if (tid == 0) sm.ticket = atomicAdd(&g_ticket, 1u);
        __syncthreads();
        unsigned int c = sm.ticket;
        if (c >= CHUNKS) break;

        // ---- decode 8-tile chunk (tiles are 128 rows x 64 cols) ----
        int ti, tj0, len, verA, verB, b;
        bool sym;
        if (c < XY_CHUNKS) {
            int seg = c >> 3, q = c & 7;
            b = seg / 31; ti = seg - b * 31;
            tj0 = q * 8; len = (q < 7) ? 8 : 6;      // 62 B-tiles per strip
            sym = false; verA = 0; verB = 3;
        } else {
            int d = (int)c - XY_CHUNKS;
            int g = d / SYM_CHUNKS_PER;
            int r = d - g * SYM_CHUNKS_PER;
            int kind = g >> 3; b = g & 7;
            int i = 0;
            for (;;) {
                int cpr = (2 * i + 9) >> 3;          // ceil((2i+2)/8)
                if (r < cpr) break;
                r -= cpr; i++;
            }
            ti = i;
            tj0 = r * 8;
            len = min(8, 2 * i + 2 - tj0);
            sym = true; verA = kind; verB = 2 + kind;
        }

        const uint4* bbase = g_stage + ((verB * BATCH + b) * NROWS) * ROW_U4;

        // ---- prologue: A (8KB) + first B pair (slots 0,1; 4KB each) ----
        {
            const uint4* asrc = g_stage + ((verA * BATCH + b) * NROWS + ti * TILE) * ROW_U4;
            cp_async16(a_base + (uint32_t)(tid * 16), asrc + tid);
            cp_async16(a_base + (uint32_t)((tid + 256) * 16), asrc + tid + 256);
            const uint4* b0src = bbase + (tj0 * BTILE) * ROW_U4;
            cp_async16(b_ring + (uint32_t)(tid * 16), b0src + tid);
            if (len > 1) {
                const uint4* b1src = bbase + ((tj0 + 1) * BTILE) * ROW_U4;
                cp_async16(b_ring + (uint32_t)(4096 + tid * 16), b1src + tid);
            }
            CP_COMMIT();
        }

        bool afload = false;
        for (int jp = 0; jp < len; jp += 2) {
            CP_WAIT0();
            __syncthreads();                 // pair visible; prev pair slots free
            int pg = (jp >> 1) & 1;
            if (jp + 2 < len) {
                int og = pg ^ 1;
                uint32_t nb = b_ring + (uint32_t)(og * 2 * 4096);
                const uint4* bs = bbase + ((tj0 + jp + 2) * BTILE) * ROW_U4;
                cp_async16(nb + (uint32_t)(tid * 16), bs + tid);
                if (jp + 3 < len) {
                    const uint4* bs2 = bbase + ((tj0 + jp + 3) * BTILE) * ROW_U4;
                    cp_async16(nb + (uint32_t)(4096 + tid * 16), bs2 + tid);
                }
                CP_COMMIT();
            }
            if (!afload) {
                #pragma unroll
                for (int mt = 0; mt < 2; mt++)
                    #pragma unroll
                    for (int k = 0; k < 2; k++)
                        ldsm_x4(af[mt][k][0], af[mt][k][1], af[mt][k][2], af[mt][k][3],
                                a_base + offA[mt][k]);
                afload = true;
            }
            compute_tile(pg * 2, ti, tj0 + jp, sym);
            if (jp + 1 < len)
                compute_tile(pg * 2 + 1, ti, tj0 + jp + 1, sym);
        }
    }

    // ================= Phase 3: reduce + finalize =================
    #pragma unroll
    for (int o = 16; o; o >>= 1) s += __shfl_xor_sync(0xffffffffu, s, o);
    if (lane == 0) sm.red[wid] = s;
    __syncthreads();
    if (tid == 0) {
        float tot = 0.0f;
        #pragma unroll
        for (int i2 = 0; i2 < 8; i2++) tot += sm.red[i2];
        g_partials[blockIdx.x] = tot;
        __threadfence();
        unsigned int old = atomicAdd(&g_done, 1u);
        sm.lastflag = (old == WORKERS - 1) ? 1u : 0u;
    }
    __syncthreads();
    if (sm.lastflag) {
        __threadfence();
        float v = 0.0f;
        for (int i = tid; i < WORKERS; i += 256) v += g_partials[i];
        #pragma unroll
        for (int o = 16; o; o >>= 1) v += __shfl_xor_sync(0xffffffffu, v, o);
        if (lane == 0) sm.red[wid] = v;
        __syncthreads();
        if (tid == 0) {
            float tot = 0.0f;
            #pragma unroll
            for (int i2 = 0; i2 < 8; i2++) tot += sm.red[i2];
            out[0] = tot * (float)(1.0 / (8.0 * 3844.0 * 3844.0));
            g_bar1 = 0u;
            g_ticket = 0u;
            __threadfence();
            g_done = 0u;
        }
    }
}

extern "C" void kernel_launch(void* const* d_in, const int* in_sizes, int n_in,
                              void* d_out, int out_size) {
    const float* x = (const float*)d_in[0];
    const float* y = (const float*)d_in[1];
    mmd_fused<<<WORKERS, 256>>>(x, y, (float*)d_out);
}